// round 6
// baseline (speedup 1.0000x reference)
#include <cuda_runtime.h>
#include <cstdint>

// ---------------------------------------------------------------------------
// f = -d( sum(mlp(pos)) )/dpos for a 2->8->4->2 ReLU MLP.
//
// Key identity: given the layer-1 ReLU mask m1 (8 bits), the layer-2
// pre-activation is affine in (x, y):
//     h2p_j = c_j(m1) + a_j(m1) x + b_j(m1) y
//     a_j = sum_{k active} W2[j][k] W1[k][0]
//     b_j = sum_{k active} W2[j][k] W1[k][1]
//     c_j = b2[j] + sum_{k active} W2[j][k] b1[k]
// and the force is
//     force = - sum_j [h2p_j > 0] * g3_j * (a_j, b_j),   g3_j = W3[0][j]+W3[1][j]
// So one 256-entry table of (GA, GB, GC) = (-g3*a, -g3*b, -g3*c) gives BOTH
// v_j = GC + GA x + GB y = -g3_j h2p_j (sign test, with per-j sign constant K)
// and the force terms (GA, GB) directly. W2/b2/W3 never live in registers.
// ---------------------------------------------------------------------------

__device__ __forceinline__ unsigned prmt_(unsigned a, unsigned b, unsigned sel) {
    unsigned d;
    asm("prmt.b32 %0, %1, %2, %3;" : "=r"(d) : "r"(a), "r"(b), "r"(sel));
    return d;
}
__device__ __forceinline__ int dp4a_(unsigned a, unsigned b, int c) {
    int d;
    asm("dp4a.u32.u32 %0, %1, %2, %3;" : "=r"(d) : "r"(a), "r"(b), "r"(c));
    return d;
}

struct W1regs { float w1x[8], w1y[8], bb1[8]; };  // 24 registers total

__device__ __forceinline__ float2 force_one(float x, float y,
                                            const W1regs& W,
                                            const float4* __restrict__ tab4,
                                            const unsigned K0, const unsigned K1,
                                            const unsigned K2, const unsigned K3) {
    // ---- layer 1 pre-activations (same FMA order as prior rounds -> same masks)
    float h1p[8];
#pragma unroll
    for (int k = 0; k < 8; k++)
        h1p[k] = fmaf(x, W.w1x[k], fmaf(y, W.w1y[k], W.bb1[k]));

    // ---- pack m1: bit k = 1 iff h1p[k] < 0 (inactive)
    unsigned a01 = prmt_(__float_as_uint(h1p[0]), __float_as_uint(h1p[1]), 0x00FBu);
    unsigned a23 = prmt_(__float_as_uint(h1p[2]), __float_as_uint(h1p[3]), 0x00FBu);
    unsigned a45 = prmt_(__float_as_uint(h1p[4]), __float_as_uint(h1p[5]), 0x00FBu);
    unsigned a67 = prmt_(__float_as_uint(h1p[6]), __float_as_uint(h1p[7]), 0x00FBu);
    unsigned tLo = prmt_(a01, a23, 0x5410u) & 0x01010101u;   // signs h1p[0..3]
    unsigned tHi = prmt_(a45, a67, 0x5410u) & 0x01010101u;   // signs h1p[4..7]
    int m1 = dp4a_(tHi, 0x80402010u, dp4a_(tLo, 0x08040201u, 0));  // 0..255

    // ---- fetch affine coefficients for this cell (3 x LDS.128)
    const float4* e = tab4 + (m1 << 2);
    float4 GA = e[0];   // -g3_j * a_j   (j = x,y,z,w)
    float4 GB = e[1];   // -g3_j * b_j
    float4 GC = e[2];   // -g3_j * c_j

    // ---- v_j = -g3_j * h2p_j
    float v0 = fmaf(x, GA.x, fmaf(y, GB.x, GC.x));
    float v1 = fmaf(x, GA.y, fmaf(y, GB.y, GC.y));
    float v2 = fmaf(x, GA.z, fmaf(y, GB.z, GC.z));
    float v3 = fmaf(x, GA.w, fmaf(y, GB.w, GC.w));

    // keep_j = all-ones iff h2p_j > 0:  keep = asr(v_j,31) ^ K_j
    // (K_j = ~0 if g3_j < 0 else 0).  masked = GA & (s ^ K) -> single LOP3.
    unsigned s0 = (unsigned)(((int)__float_as_int(v0)) >> 31);
    unsigned s1 = (unsigned)(((int)__float_as_int(v1)) >> 31);
    unsigned s2 = (unsigned)(((int)__float_as_int(v2)) >> 31);
    unsigned s3 = (unsigned)(((int)__float_as_int(v3)) >> 31);

    float fx, fy;
    fx  = __uint_as_float(__float_as_uint(GA.x) & (s0 ^ K0));
    fy  = __uint_as_float(__float_as_uint(GB.x) & (s0 ^ K0));
    fx += __uint_as_float(__float_as_uint(GA.y) & (s1 ^ K1));
    fy += __uint_as_float(__float_as_uint(GB.y) & (s1 ^ K1));
    fx += __uint_as_float(__float_as_uint(GA.z) & (s2 ^ K2));
    fy += __uint_as_float(__float_as_uint(GB.z) & (s2 ^ K2));
    fx += __uint_as_float(__float_as_uint(GA.w) & (s3 ^ K3));
    fy += __uint_as_float(__float_as_uint(GB.w) & (s3 ^ K3));
    return make_float2(fx, fy);   // negation folded into the table
}

__global__ __launch_bounds__(256, 4)
void toy_force_kernel(const float4* __restrict__ pos4,
                      const float* __restrict__ W1,
                      const float* __restrict__ b1,
                      const float* __restrict__ W2,
                      const float* __restrict__ b2,
                      const float* __restrict__ W3,
                      float4* __restrict__ out4,
                      int n4) {
    __shared__ float4 tab4[256 * 4];   // entry m1: [GA(4), GB(4), GC(4), pad(4)] = 64B

    int t = threadIdx.x;

    // Prefetch this thread's two float4s first: DRAM latency overlaps the
    // table build + barrier below.
    int base = blockIdx.x * (256 * 2) + t;
    int i0 = base, i1 = base + 256;
    bool valid0 = (i0 < n4), valid1 = (i1 < n4);
    float4 p0 = make_float4(0.f, 0.f, 0.f, 0.f), p1 = p0;
    if (valid0) p0 = __ldg(&pos4[i0]);
    if (valid1) p1 = __ldg(&pos4[i1]);

    // ---- g3 and its sign constants
    float g3[4];
    unsigned Ks[4];
#pragma unroll
    for (int j = 0; j < 4; j++) {
        g3[j] = W3[j] + W3[4 + j];          // W3 is [2,4] row-major
        Ks[j] = (g3[j] < 0.0f) ? 0xFFFFFFFFu : 0u;
    }

    // ---- build coefficient table: thread t owns mask m1 = t
    {
        float* e = reinterpret_cast<float*>(&tab4[t << 2]);
#pragma unroll
        for (int j = 0; j < 4; j++) {
            float a = 0.f, b = 0.f, c = b2[j];
#pragma unroll
            for (int k = 0; k < 8; k++) {
                if (!((t >> k) & 1)) {      // m1 bit clear -> neuron k active
                    float w = W2[j * 8 + k];
                    a = fmaf(w, W1[k * 2 + 0], a);
                    b = fmaf(w, W1[k * 2 + 1], b);
                    c = fmaf(w, b1[k], c);
                }
            }
            e[j]     = -g3[j] * a;          // GA
            e[4 + j] = -g3[j] * b;          // GB
            e[8 + j] = -g3[j] * c;          // GC
        }
    }

    // ---- layer-1 weights in registers (24 regs; W2/b2/W3 stay in the table)
    W1regs W;
#pragma unroll
    for (int k = 0; k < 8; k++) {
        W.w1x[k] = W1[k * 2 + 0];
        W.w1y[k] = W1[k * 2 + 1];
        W.bb1[k] = b1[k];
    }
    __syncthreads();

    if (valid0) {
        float2 f0 = force_one(p0.x, p0.y, W, tab4, Ks[0], Ks[1], Ks[2], Ks[3]);
        float2 f1 = force_one(p0.z, p0.w, W, tab4, Ks[0], Ks[1], Ks[2], Ks[3]);
        out4[i0] = make_float4(f0.x, f0.y, f1.x, f1.y);
    }
    if (valid1) {
        float2 f0 = force_one(p1.x, p1.y, W, tab4, Ks[0], Ks[1], Ks[2], Ks[3]);
        float2 f1 = force_one(p1.z, p1.w, W, tab4, Ks[0], Ks[1], Ks[2], Ks[3]);
        out4[i1] = make_float4(f0.x, f0.y, f1.x, f1.y);
    }
}

extern "C" void kernel_launch(void* const* d_in, const int* in_sizes, int n_in,
                              void* d_out, int out_size) {
    const float* pos = (const float*)d_in[0];   // [N,2] float32
    const float* W1  = (const float*)d_in[1];   // [8,2]
    const float* b1  = (const float*)d_in[2];   // [8]
    const float* W2  = (const float*)d_in[3];   // [4,8]
    const float* b2  = (const float*)d_in[4];   // [4]
    const float* W3  = (const float*)d_in[5];   // [2,4]
    float* out = (float*)d_out;                 // [N,2] float32

    int n4 = in_sizes[0] / 4;                   // float4s (2 positions each)
    const int threads = 256;
    const int per_block = threads * 2;          // 2 float4 per thread
    int blocks = (n4 + per_block - 1) / per_block;

    toy_force_kernel<<<blocks, threads>>>(
        (const float4*)pos, W1, b1, W2, b2, W3, (float4*)out, n4);
}

// round 7
// speedup vs baseline: 2.0603x; 2.0603x over previous
#include <cuda_runtime.h>
#include <cstdint>

// ---------------------------------------------------------------------------
// f = -d( sum(mlp(pos)) )/dpos for a 2->8->4->2 ReLU MLP.
//
// The force is piecewise constant in the ReLU masks (m1: 8 bits, m2: 4 bits):
//   force(m1,m2) = -sum_{k: m1_k active} v[m2][k] * W1[k,:]
//   v[m2][k]     =  sum_{j: m2_j active} g3_j * W2[j][k],  g3_j = W3[0][j]+W3[1][j]
// One merged 4096-entry table  tab[(m2<<8)|m1] -> float2 (negation folded in),
// 32KB smem, a single data-dependent LDS.64 per position (8 B/pos).
// Forward pass packed 2-neurons-per-lane with fma.rn.f32x2 (exact fp32/half).
// ---------------------------------------------------------------------------

typedef unsigned long long u64;

__device__ __forceinline__ unsigned prmt_(unsigned a, unsigned b, unsigned sel) {
    unsigned d;
    asm("prmt.b32 %0, %1, %2, %3;" : "=r"(d) : "r"(a), "r"(b), "r"(sel));
    return d;
}
__device__ __forceinline__ int dp4a_(unsigned a, unsigned b, int c) {
    int d;
    asm("dp4a.u32.u32 %0, %1, %2, %3;" : "=r"(d) : "r"(a), "r"(b), "r"(c));
    return d;
}
__device__ __forceinline__ u64 pack2_(float lo, float hi) {
    u64 r;
    asm("mov.b64 %0, {%1, %2};" : "=l"(r) : "f"(lo), "f"(hi));
    return r;
}
__device__ __forceinline__ void unpack2_(u64 v, float& lo, float& hi) {
    asm("mov.b64 {%0, %1}, %2;" : "=f"(lo), "=f"(hi) : "l"(v));
}
__device__ __forceinline__ u64 fma2_(u64 a, u64 b, u64 c) {
    u64 d;
    asm("fma.rn.f32x2 %0, %1, %2, %3;" : "=l"(d) : "l"(a), "l"(b), "l"(c));
    return d;
}
__device__ __forceinline__ u64 mul2_(u64 a, u64 b) {
    u64 d;
    asm("mul.rn.f32x2 %0, %1, %2;" : "=l"(d) : "l"(a), "l"(b));
    return d;
}

struct Wts {
    u64 w1x2[4], w1y2[4], b12[4];   // neuron pairs (2i, 2i+1): 24 regs
    u64 w2p[4][4];                   // W2[j][2i..2i+1] packed:   32 regs
    float b2[4];                     //                             4 regs
};

__device__ __forceinline__ float2 force_one(float x, float y, const Wts& W,
                                            const float2* __restrict__ tab) {
    u64 xx = pack2_(x, x), yy = pack2_(y, y);

    // ---- layer 1 pre-activations, 2 neurons per FFMA2 ----
    u64 h1p2[4];
#pragma unroll
    for (int i = 0; i < 4; i++)
        h1p2[i] = fma2_(xx, W.w1x2[i], fma2_(yy, W.w1y2[i], W.b12[i]));

    float h1p[8];
#pragma unroll
    for (int i = 0; i < 4; i++) unpack2_(h1p2[i], h1p[2 * i], h1p[2 * i + 1]);

    // ---- m1: bit k = 1 iff h1p[k] < 0 (inactive) ----
    unsigned a01 = prmt_(__float_as_uint(h1p[0]), __float_as_uint(h1p[1]), 0x00FBu);
    unsigned a23 = prmt_(__float_as_uint(h1p[2]), __float_as_uint(h1p[3]), 0x00FBu);
    unsigned a45 = prmt_(__float_as_uint(h1p[4]), __float_as_uint(h1p[5]), 0x00FBu);
    unsigned a67 = prmt_(__float_as_uint(h1p[6]), __float_as_uint(h1p[7]), 0x00FBu);
    unsigned tLo = prmt_(a01, a23, 0x5410u) & 0x01010101u;
    unsigned tHi = prmt_(a45, a67, 0x5410u) & 0x01010101u;
    int m1 = dp4a_(tHi, 0x80402010u, dp4a_(tLo, 0x08040201u, 0));   // 0..255

    // ---- relu + repack ----
    u64 h1_2[4];
#pragma unroll
    for (int i = 0; i < 4; i++)
        h1_2[i] = pack2_(fmaxf(h1p[2 * i], 0.0f), fmaxf(h1p[2 * i + 1], 0.0f));

    // ---- layer 2 pre-activations (signs only), packed dot products ----
    float h2p[4];
#pragma unroll
    for (int j = 0; j < 4; j++) {
        u64 acc = mul2_(h1_2[0], W.w2p[j][0]);
        acc = fma2_(h1_2[1], W.w2p[j][1], acc);
        acc = fma2_(h1_2[2], W.w2p[j][2], acc);
        acc = fma2_(h1_2[3], W.w2p[j][3], acc);
        float l, h;
        unpack2_(acc, l, h);
        h2p[j] = (l + h) + W.b2[j];
    }

    // ---- m2: bit j = 1 iff h2p[j] < 0 (inactive) ----
    unsigned b01 = prmt_(__float_as_uint(h2p[0]), __float_as_uint(h2p[1]), 0x00FBu);
    unsigned b23 = prmt_(__float_as_uint(h2p[2]), __float_as_uint(h2p[3]), 0x00FBu);
    unsigned bm  = prmt_(b01, b23, 0x5410u) & 0x01010101u;
    int m2 = dp4a_(bm, 0x08040201u, 0);                              // 0..15

    return tab[(m2 << 8) | m1];   // force, negation folded into the table
}

__global__ __launch_bounds__(256, 3)
void toy_force_kernel(const float4* __restrict__ pos4,
                      const float* __restrict__ W1,
                      const float* __restrict__ b1,
                      const float* __restrict__ W2,
                      const float* __restrict__ b2,
                      const float* __restrict__ W3,
                      float4* __restrict__ out4,
                      int n4) {
    __shared__ float2 tab[4096];   // [(m2<<8) | m1] -> -force

    int t = threadIdx.x;

    // Prefetch this thread's data; DRAM latency overlaps table build + barrier.
    int base = blockIdx.x * (256 * 2) + t;
    int i0 = base, i1 = base + 256;
    bool valid0 = (i0 < n4), valid1 = (i1 < n4);
    float4 p0 = make_float4(0.f, 0.f, 0.f, 0.f), p1 = p0;
    if (valid0) p0 = __ldg(&pos4[i0]);
    if (valid1) p1 = __ldg(&pos4[i1]);

    // ---- build the merged force table ----
    // Thread t owns (m2 = t>>4, m1_lo4 = t&15); loops over m1_hi4.
    // Stores: lanes write consecutive float2s -> conflict-free STS.
    {
        float g3[4];
#pragma unroll
        for (int j = 0; j < 4; j++) g3[j] = W3[j] + W3[4 + j];  // W3 [2,4] row-major

        int m2  = t >> 4;
        int lo4 = t & 15;

        float v[8];
#pragma unroll
        for (int k = 0; k < 8; k++) {
            float s = 0.f;
#pragma unroll
            for (int j = 0; j < 4; j++)
                if (!((m2 >> j) & 1)) s = fmaf(g3[j], W2[j * 8 + k], s);
            v[k] = s;
        }

        float lx = 0.f, ly = 0.f;          // contribution of neurons 0..3 (fixed)
#pragma unroll
        for (int k = 0; k < 4; k++) {
            if (!((lo4 >> k) & 1)) {
                lx = fmaf(v[k], W1[2 * k + 0], lx);
                ly = fmaf(v[k], W1[2 * k + 1], ly);
            }
        }

        int ebase = (m2 << 8) | lo4;
#pragma unroll
        for (int hi = 0; hi < 16; hi++) {
            float fx = lx, fy = ly;
#pragma unroll
            for (int k = 0; k < 4; k++) {
                if (!((hi >> k) & 1)) {
                    fx = fmaf(v[k + 4], W1[2 * (k + 4) + 0], fx);
                    fy = fmaf(v[k + 4], W1[2 * (k + 4) + 1], fy);
                }
            }
            tab[ebase | (hi << 4)] = make_float2(-fx, -fy);
        }
    }

    // ---- packed weights in registers ----
    Wts W;
#pragma unroll
    for (int i = 0; i < 4; i++) {
        W.w1x2[i] = pack2_(W1[4 * i + 0], W1[4 * i + 2]);
        W.w1y2[i] = pack2_(W1[4 * i + 1], W1[4 * i + 3]);
        W.b12[i]  = pack2_(b1[2 * i], b1[2 * i + 1]);
    }
#pragma unroll
    for (int j = 0; j < 4; j++) {
        W.b2[j] = b2[j];
#pragma unroll
        for (int i = 0; i < 4; i++)
            W.w2p[j][i] = pack2_(W2[j * 8 + 2 * i], W2[j * 8 + 2 * i + 1]);
    }
    __syncthreads();

    if (valid0) {
        float2 f0 = force_one(p0.x, p0.y, W, tab);
        float2 f1 = force_one(p0.z, p0.w, W, tab);
        out4[i0] = make_float4(f0.x, f0.y, f1.x, f1.y);
    }
    if (valid1) {
        float2 f0 = force_one(p1.x, p1.y, W, tab);
        float2 f1 = force_one(p1.z, p1.w, W, tab);
        out4[i1] = make_float4(f0.x, f0.y, f1.x, f1.y);
    }
}

extern "C" void kernel_launch(void* const* d_in, const int* in_sizes, int n_in,
                              void* d_out, int out_size) {
    const float* pos = (const float*)d_in[0];   // [N,2] float32
    const float* W1  = (const float*)d_in[1];   // [8,2]
    const float* b1  = (const float*)d_in[2];   // [8]
    const float* W2  = (const float*)d_in[3];   // [4,8]
    const float* b2  = (const float*)d_in[4];   // [4]
    const float* W3  = (const float*)d_in[5];   // [2,4]
    float* out = (float*)d_out;                 // [N,2] float32

    int n4 = in_sizes[0] / 4;                   // float4s (2 positions each)
    const int threads = 256;
    const int per_block = threads * 2;          // 2 float4 per thread
    int blocks = (n4 + per_block - 1) / per_block;

    toy_force_kernel<<<blocks, threads>>>(
        (const float4*)pos, W1, b1, W2, b2, W3, (float4*)out, n4);
}

// round 8
// speedup vs baseline: 2.2063x; 1.0709x over previous
#include <cuda_runtime.h>
#include <cstdint>

// ---------------------------------------------------------------------------
// f = -d( sum(mlp(pos)) )/dpos for a 2->8->4->2 ReLU MLP.
//
// Force is piecewise constant in the ReLU masks (m1: 8 bits, m2: 4 bits):
//   force(m1,m2) = -sum_{k: m1_k active} v[m2][k] * W1[k,:]
//   v[m2][k]     =  sum_{j: m2_j active} g3_j * W2[j][k],  g3_j = W3[0][j]+W3[1][j]
// Merged 4096-entry smem table  tab[(m2<<8)|m1] -> float2 (negation folded).
// Forward packed 2-neurons-per-lane with fma.rn.f32x2.
// Round 8: 4 float4 per thread (8 positions), loads front-batched -> enough
// ILP to hide DRAM + LDS latency at 2 CTAs/SM (latency-bound fix).
// ---------------------------------------------------------------------------

typedef unsigned long long u64;

__device__ __forceinline__ unsigned prmt_(unsigned a, unsigned b, unsigned sel) {
    unsigned d;
    asm("prmt.b32 %0, %1, %2, %3;" : "=r"(d) : "r"(a), "r"(b), "r"(sel));
    return d;
}
__device__ __forceinline__ int dp4a_(unsigned a, unsigned b, int c) {
    int d;
    asm("dp4a.u32.u32 %0, %1, %2, %3;" : "=r"(d) : "r"(a), "r"(b), "r"(c));
    return d;
}
__device__ __forceinline__ u64 pack2_(float lo, float hi) {
    u64 r;
    asm("mov.b64 %0, {%1, %2};" : "=l"(r) : "f"(lo), "f"(hi));
    return r;
}
__device__ __forceinline__ void unpack2_(u64 v, float& lo, float& hi) {
    asm("mov.b64 {%0, %1}, %2;" : "=f"(lo), "=f"(hi) : "l"(v));
}
__device__ __forceinline__ u64 fma2_(u64 a, u64 b, u64 c) {
    u64 d;
    asm("fma.rn.f32x2 %0, %1, %2, %3;" : "=l"(d) : "l"(a), "l"(b), "l"(c));
    return d;
}
__device__ __forceinline__ u64 mul2_(u64 a, u64 b) {
    u64 d;
    asm("mul.rn.f32x2 %0, %1, %2;" : "=l"(d) : "l"(a), "l"(b));
    return d;
}

struct Wts {
    u64 w1x2[4], w1y2[4], b12[4];   // neuron pairs (2i, 2i+1)
    u64 w2p[4][4];                   // W2[j][2i..2i+1] packed
    float b2[4];
};

__device__ __forceinline__ float2 force_one(float x, float y, const Wts& W,
                                            const float2* __restrict__ tab) {
    u64 xx = pack2_(x, x), yy = pack2_(y, y);

    // ---- layer 1 pre-activations, 2 neurons per FFMA2 ----
    u64 h1p2[4];
#pragma unroll
    for (int i = 0; i < 4; i++)
        h1p2[i] = fma2_(xx, W.w1x2[i], fma2_(yy, W.w1y2[i], W.b12[i]));

    float h1p[8];
#pragma unroll
    for (int i = 0; i < 4; i++) unpack2_(h1p2[i], h1p[2 * i], h1p[2 * i + 1]);

    // ---- m1: bit k = 1 iff h1p[k] < 0 (inactive) ----
    unsigned a01 = prmt_(__float_as_uint(h1p[0]), __float_as_uint(h1p[1]), 0x00FBu);
    unsigned a23 = prmt_(__float_as_uint(h1p[2]), __float_as_uint(h1p[3]), 0x00FBu);
    unsigned a45 = prmt_(__float_as_uint(h1p[4]), __float_as_uint(h1p[5]), 0x00FBu);
    unsigned a67 = prmt_(__float_as_uint(h1p[6]), __float_as_uint(h1p[7]), 0x00FBu);
    unsigned tLo = prmt_(a01, a23, 0x5410u) & 0x01010101u;
    unsigned tHi = prmt_(a45, a67, 0x5410u) & 0x01010101u;
    int m1 = dp4a_(tHi, 0x80402010u, dp4a_(tLo, 0x08040201u, 0));   // 0..255

    // ---- relu + repack ----
    u64 h1_2[4];
#pragma unroll
    for (int i = 0; i < 4; i++)
        h1_2[i] = pack2_(fmaxf(h1p[2 * i], 0.0f), fmaxf(h1p[2 * i + 1], 0.0f));

    // ---- layer 2 pre-activations (signs only) ----
    float h2p[4];
#pragma unroll
    for (int j = 0; j < 4; j++) {
        u64 acc = mul2_(h1_2[0], W.w2p[j][0]);
        acc = fma2_(h1_2[1], W.w2p[j][1], acc);
        acc = fma2_(h1_2[2], W.w2p[j][2], acc);
        acc = fma2_(h1_2[3], W.w2p[j][3], acc);
        float l, h;
        unpack2_(acc, l, h);
        h2p[j] = (l + h) + W.b2[j];
    }

    // ---- m2: bit j = 1 iff h2p[j] < 0 (inactive) ----
    unsigned b01 = prmt_(__float_as_uint(h2p[0]), __float_as_uint(h2p[1]), 0x00FBu);
    unsigned b23 = prmt_(__float_as_uint(h2p[2]), __float_as_uint(h2p[3]), 0x00FBu);
    unsigned bm  = prmt_(b01, b23, 0x5410u) & 0x01010101u;
    int m2 = dp4a_(bm, 0x08040201u, 0);                              // 0..15

    return tab[(m2 << 8) | m1];   // negation folded into the table
}

#define ILP 4

__global__ __launch_bounds__(256, 2)
void toy_force_kernel(const float4* __restrict__ pos4,
                      const float* __restrict__ W1,
                      const float* __restrict__ b1,
                      const float* __restrict__ W2,
                      const float* __restrict__ b2,
                      const float* __restrict__ W3,
                      float4* __restrict__ out4,
                      int n4) {
    __shared__ float2 tab[4096];   // [(m2<<8) | m1] -> -force

    int t = threadIdx.x;

    // ---- front-batched loads: ILP x LDG.128 in flight (MLP_p1 = ILP) ----
    int base = blockIdx.x * (256 * ILP) + t;
    bool full = (blockIdx.x * (256 * ILP) + 256 * ILP) <= n4;  // uniform branch

    float4 p[ILP];
#pragma unroll
    for (int i = 0; i < ILP; i++) p[i] = make_float4(0.f, 0.f, 0.f, 0.f);

    if (full) {
#pragma unroll
        for (int i = 0; i < ILP; i++) p[i] = __ldg(&pos4[base + i * 256]);
    } else {
#pragma unroll
        for (int i = 0; i < ILP; i++)
            if (base + i * 256 < n4) p[i] = __ldg(&pos4[base + i * 256]);
    }

    // ---- build the merged force table (overlaps LDG latency) ----
    {
        float g3[4];
#pragma unroll
        for (int j = 0; j < 4; j++) g3[j] = W3[j] + W3[4 + j];  // W3 [2,4] row-major

        int m2  = t >> 4;
        int lo4 = t & 15;

        float v[8];
#pragma unroll
        for (int k = 0; k < 8; k++) {
            float s = 0.f;
#pragma unroll
            for (int j = 0; j < 4; j++)
                if (!((m2 >> j) & 1)) s = fmaf(g3[j], W2[j * 8 + k], s);
            v[k] = s;
        }

        float lx = 0.f, ly = 0.f;          // neurons 0..3 (fixed per thread)
#pragma unroll
        for (int k = 0; k < 4; k++) {
            if (!((lo4 >> k) & 1)) {
                lx = fmaf(v[k], W1[2 * k + 0], lx);
                ly = fmaf(v[k], W1[2 * k + 1], ly);
            }
        }

        int ebase = (m2 << 8) | lo4;
#pragma unroll
        for (int hi = 0; hi < 16; hi++) {
            float fx = lx, fy = ly;
#pragma unroll
            for (int k = 0; k < 4; k++) {
                if (!((hi >> k) & 1)) {
                    fx = fmaf(v[k + 4], W1[2 * (k + 4) + 0], fx);
                    fy = fmaf(v[k + 4], W1[2 * (k + 4) + 1], fy);
                }
            }
            tab[ebase | (hi << 4)] = make_float2(-fx, -fy);
        }
    }

    // ---- packed weights in registers ----
    Wts W;
#pragma unroll
    for (int i = 0; i < 4; i++) {
        W.w1x2[i] = pack2_(W1[4 * i + 0], W1[4 * i + 2]);
        W.w1y2[i] = pack2_(W1[4 * i + 1], W1[4 * i + 3]);
        W.b12[i]  = pack2_(b1[2 * i], b1[2 * i + 1]);
    }
#pragma unroll
    for (int j = 0; j < 4; j++) {
        W.b2[j] = b2[j];
#pragma unroll
        for (int i = 0; i < 4; i++)
            W.w2p[j][i] = pack2_(W2[j * 8 + 2 * i], W2[j * 8 + 2 * i + 1]);
    }
    __syncthreads();

    // ---- compute 2*ILP independent positions, then store ----
    if (full) {
#pragma unroll
        for (int i = 0; i < ILP; i++) {
            float2 f0 = force_one(p[i].x, p[i].y, W, tab);
            float2 f1 = force_one(p[i].z, p[i].w, W, tab);
            out4[base + i * 256] = make_float4(f0.x, f0.y, f1.x, f1.y);
        }
    } else {
#pragma unroll
        for (int i = 0; i < ILP; i++) {
            if (base + i * 256 < n4) {
                float2 f0 = force_one(p[i].x, p[i].y, W, tab);
                float2 f1 = force_one(p[i].z, p[i].w, W, tab);
                out4[base + i * 256] = make_float4(f0.x, f0.y, f1.x, f1.y);
            }
        }
    }
}

extern "C" void kernel_launch(void* const* d_in, const int* in_sizes, int n_in,
                              void* d_out, int out_size) {
    const float* pos = (const float*)d_in[0];   // [N,2] float32
    const float* W1  = (const float*)d_in[1];   // [8,2]
    const float* b1  = (const float*)d_in[2];   // [8]
    const float* W2  = (const float*)d_in[3];   // [4,8]
    const float* b2  = (const float*)d_in[4];   // [4]
    const float* W3  = (const float*)d_in[5];   // [2,4]
    float* out = (float*)d_out;                 // [N,2] float32

    int n4 = in_sizes[0] / 4;                   // float4s (2 positions each)
    const int threads = 256;
    const int per_block = threads * ILP;        // ILP float4 per thread
    int blocks = (n4 + per_block - 1) / per_block;

    toy_force_kernel<<<blocks, threads>>>(
        (const float4*)pos, W1, b1, W2, b2, W3, (float4*)out, n4);
}

// round 9
// speedup vs baseline: 2.2261x; 1.0089x over previous
#include <cuda_runtime.h>
#include <cstdint>

// ---------------------------------------------------------------------------
// f = -d( sum(mlp(pos)) )/dpos for a 2->8->4->2 ReLU MLP.
//
// Force is piecewise constant in the ReLU masks (m1: 8 bits, m2: 4 bits):
//   force(m1,m2) = -sum_{k: m1_k active} v[m2][k] * W1[k,:]
//   v[m2][k]     =  sum_{j: m2_j active} g3_j * W2[j][k],  g3_j = W3[0][j]+W3[1][j]
// Merged 4096-entry smem table  tab[(m2<<8)|m1] -> float2 (negation folded).
// Forward packed 2-neurons-per-lane with fma.rn.f32x2.
// Round 8: 4 float4 per thread (8 positions), loads front-batched -> enough
// ILP to hide DRAM + LDS latency at 2 CTAs/SM (latency-bound fix).
// ---------------------------------------------------------------------------

typedef unsigned long long u64;

__device__ __forceinline__ unsigned prmt_(unsigned a, unsigned b, unsigned sel) {
    unsigned d;
    asm("prmt.b32 %0, %1, %2, %3;" : "=r"(d) : "r"(a), "r"(b), "r"(sel));
    return d;
}
__device__ __forceinline__ int dp4a_(unsigned a, unsigned b, int c) {
    int d;
    asm("dp4a.u32.u32 %0, %1, %2, %3;" : "=r"(d) : "r"(a), "r"(b), "r"(c));
    return d;
}
__device__ __forceinline__ u64 pack2_(float lo, float hi) {
    u64 r;
    asm("mov.b64 %0, {%1, %2};" : "=l"(r) : "f"(lo), "f"(hi));
    return r;
}
__device__ __forceinline__ void unpack2_(u64 v, float& lo, float& hi) {
    asm("mov.b64 {%0, %1}, %2;" : "=f"(lo), "=f"(hi) : "l"(v));
}
__device__ __forceinline__ u64 fma2_(u64 a, u64 b, u64 c) {
    u64 d;
    asm("fma.rn.f32x2 %0, %1, %2, %3;" : "=l"(d) : "l"(a), "l"(b), "l"(c));
    return d;
}
__device__ __forceinline__ u64 mul2_(u64 a, u64 b) {
    u64 d;
    asm("mul.rn.f32x2 %0, %1, %2;" : "=l"(d) : "l"(a), "l"(b));
    return d;
}

struct Wts {
    u64 w1x2[4], w1y2[4], b12[4];   // neuron pairs (2i, 2i+1)
    u64 w2p[4][4];                   // W2[j][2i..2i+1] packed
    float b2[4];
};

__device__ __forceinline__ float2 force_one(float x, float y, const Wts& W,
                                            const float2* __restrict__ tab) {
    u64 xx = pack2_(x, x), yy = pack2_(y, y);

    // ---- layer 1 pre-activations, 2 neurons per FFMA2 ----
    u64 h1p2[4];
#pragma unroll
    for (int i = 0; i < 4; i++)
        h1p2[i] = fma2_(xx, W.w1x2[i], fma2_(yy, W.w1y2[i], W.b12[i]));

    float h1p[8];
#pragma unroll
    for (int i = 0; i < 4; i++) unpack2_(h1p2[i], h1p[2 * i], h1p[2 * i + 1]);

    // ---- m1: bit k = 1 iff h1p[k] < 0 (inactive) ----
    unsigned a01 = prmt_(__float_as_uint(h1p[0]), __float_as_uint(h1p[1]), 0x00FBu);
    unsigned a23 = prmt_(__float_as_uint(h1p[2]), __float_as_uint(h1p[3]), 0x00FBu);
    unsigned a45 = prmt_(__float_as_uint(h1p[4]), __float_as_uint(h1p[5]), 0x00FBu);
    unsigned a67 = prmt_(__float_as_uint(h1p[6]), __float_as_uint(h1p[7]), 0x00FBu);
    unsigned tLo = prmt_(a01, a23, 0x5410u) & 0x01010101u;
    unsigned tHi = prmt_(a45, a67, 0x5410u) & 0x01010101u;
    int m1 = dp4a_(tHi, 0x80402010u, dp4a_(tLo, 0x08040201u, 0));   // 0..255

    // ---- relu + repack ----
    u64 h1_2[4];
#pragma unroll
    for (int i = 0; i < 4; i++)
        h1_2[i] = pack2_(fmaxf(h1p[2 * i], 0.0f), fmaxf(h1p[2 * i + 1], 0.0f));

    // ---- layer 2 pre-activations (signs only) ----
    float h2p[4];
#pragma unroll
    for (int j = 0; j < 4; j++) {
        u64 acc = mul2_(h1_2[0], W.w2p[j][0]);
        acc = fma2_(h1_2[1], W.w2p[j][1], acc);
        acc = fma2_(h1_2[2], W.w2p[j][2], acc);
        acc = fma2_(h1_2[3], W.w2p[j][3], acc);
        float l, h;
        unpack2_(acc, l, h);
        h2p[j] = (l + h) + W.b2[j];
    }

    // ---- m2: bit j = 1 iff h2p[j] < 0 (inactive) ----
    unsigned b01 = prmt_(__float_as_uint(h2p[0]), __float_as_uint(h2p[1]), 0x00FBu);
    unsigned b23 = prmt_(__float_as_uint(h2p[2]), __float_as_uint(h2p[3]), 0x00FBu);
    unsigned bm  = prmt_(b01, b23, 0x5410u) & 0x01010101u;
    int m2 = dp4a_(bm, 0x08040201u, 0);                              // 0..15

    return tab[(m2 << 8) | m1];   // negation folded into the table
}

#define ILP 4

__global__ __launch_bounds__(256, 2)
void toy_force_kernel(const float4* __restrict__ pos4,
                      const float* __restrict__ W1,
                      const float* __restrict__ b1,
                      const float* __restrict__ W2,
                      const float* __restrict__ b2,
                      const float* __restrict__ W3,
                      float4* __restrict__ out4,
                      int n4) {
    __shared__ float2 tab[4096];   // [(m2<<8) | m1] -> -force

    int t = threadIdx.x;

    // ---- front-batched loads: ILP x LDG.128 in flight (MLP_p1 = ILP) ----
    int base = blockIdx.x * (256 * ILP) + t;
    bool full = (blockIdx.x * (256 * ILP) + 256 * ILP) <= n4;  // uniform branch

    float4 p[ILP];
#pragma unroll
    for (int i = 0; i < ILP; i++) p[i] = make_float4(0.f, 0.f, 0.f, 0.f);

    if (full) {
#pragma unroll
        for (int i = 0; i < ILP; i++) p[i] = __ldg(&pos4[base + i * 256]);
    } else {
#pragma unroll
        for (int i = 0; i < ILP; i++)
            if (base + i * 256 < n4) p[i] = __ldg(&pos4[base + i * 256]);
    }

    // ---- build the merged force table (overlaps LDG latency) ----
    {
        float g3[4];
#pragma unroll
        for (int j = 0; j < 4; j++) g3[j] = W3[j] + W3[4 + j];  // W3 [2,4] row-major

        int m2  = t >> 4;
        int lo4 = t & 15;

        float v[8];
#pragma unroll
        for (int k = 0; k < 8; k++) {
            float s = 0.f;
#pragma unroll
            for (int j = 0; j < 4; j++)
                if (!((m2 >> j) & 1)) s = fmaf(g3[j], W2[j * 8 + k], s);
            v[k] = s;
        }

        float lx = 0.f, ly = 0.f;          // neurons 0..3 (fixed per thread)
#pragma unroll
        for (int k = 0; k < 4; k++) {
            if (!((lo4 >> k) & 1)) {
                lx = fmaf(v[k], W1[2 * k + 0], lx);
                ly = fmaf(v[k], W1[2 * k + 1], ly);
            }
        }

        int ebase = (m2 << 8) | lo4;
#pragma unroll
        for (int hi = 0; hi < 16; hi++) {
            float fx = lx, fy = ly;
#pragma unroll
            for (int k = 0; k < 4; k++) {
                if (!((hi >> k) & 1)) {
                    fx = fmaf(v[k + 4], W1[2 * (k + 4) + 0], fx);
                    fy = fmaf(v[k + 4], W1[2 * (k + 4) + 1], fy);
                }
            }
            tab[ebase | (hi << 4)] = make_float2(-fx, -fy);
        }
    }

    // ---- packed weights in registers ----
    Wts W;
#pragma unroll
    for (int i = 0; i < 4; i++) {
        W.w1x2[i] = pack2_(W1[4 * i + 0], W1[4 * i + 2]);
        W.w1y2[i] = pack2_(W1[4 * i + 1], W1[4 * i + 3]);
        W.b12[i]  = pack2_(b1[2 * i], b1[2 * i + 1]);
    }
#pragma unroll
    for (int j = 0; j < 4; j++) {
        W.b2[j] = b2[j];
#pragma unroll
        for (int i = 0; i < 4; i++)
            W.w2p[j][i] = pack2_(W2[j * 8 + 2 * i], W2[j * 8 + 2 * i + 1]);
    }
    __syncthreads();

    // ---- compute 2*ILP independent positions, then store ----
    if (full) {
#pragma unroll
        for (int i = 0; i < ILP; i++) {
            float2 f0 = force_one(p[i].x, p[i].y, W, tab);
            float2 f1 = force_one(p[i].z, p[i].w, W, tab);
            out4[base + i * 256] = make_float4(f0.x, f0.y, f1.x, f1.y);
        }
    } else {
#pragma unroll
        for (int i = 0; i < ILP; i++) {
            if (base + i * 256 < n4) {
                float2 f0 = force_one(p[i].x, p[i].y, W, tab);
                float2 f1 = force_one(p[i].z, p[i].w, W, tab);
                out4[base + i * 256] = make_float4(f0.x, f0.y, f1.x, f1.y);
            }
        }
    }
}

extern "C" void kernel_launch(void* const* d_in, const int* in_sizes, int n_in,
                              void* d_out, int out_size) {
    const float* pos = (const float*)d_in[0];   // [N,2] float32
    const float* W1  = (const float*)d_in[1];   // [8,2]
    const float* b1  = (const float*)d_in[2];   // [8]
    const float* W2  = (const float*)d_in[3];   // [4,8]
    const float* b2  = (const float*)d_in[4];   // [4]
    const float* W3  = (const float*)d_in[5];   // [2,4]
    float* out = (float*)d_out;                 // [N,2] float32

    int n4 = in_sizes[0] / 4;                   // float4s (2 positions each)
    const int threads = 256;
    const int per_block = threads * ILP;        // ILP float4 per thread
    int blocks = (n4 + per_block - 1) / per_block;

    toy_force_kernel<<<blocks, threads>>>(
        (const float4*)pos, W1, b1, W2, b2, W3, (float4*)out, n4);
}